// round 2
// baseline (speedup 1.0000x reference)
#include <cuda_runtime.h>
#include <math.h>

#define S_ 128
#define B_ 64
#define V_ 10000
#define E_ 256
#define H_ 512

// ---------------- scratch (device globals; no allocations allowed) ----------
__device__ float g_h0[2][B_ * H_];
__device__ float g_h1[2][B_ * H_];
__device__ float g_rz0[B_ * 2 * H_];          // [b*1024 + n], n<512 = r, n>=512 = z
__device__ float g_rz1[B_ * 2 * H_];
__device__ float g_h1all[S_ * B_ * H_];       // 16 MB: all h1(t) rows for the logits GEMM

// ---------------- parameter structs ----------------------------------------
struct GateArgs {
    const float* hprev;   // [B,512]
    const float* x;       // emb_table (layer0) or h0 current (layer1)
    const int*   idx;     // token ids for this step (layer0) or nullptr
    const float* Wr; const float* br;
    const float* Wz; const float* bz;
    float* out;           // [B,1024]
    int Kx;               // 256 (emb) or 512 (h0)
};

struct HArgs {
    const float* hprev;
    const float* x;
    const int*   idx;
    const float* rz;      // [B,1024] sigmoid'ed r|z
    const float* Wh; const float* bh;
    float* hout;          // [B,512]
    float* hout2;         // optional second copy (h1all slot) or nullptr
    int Kx;
};

// ---------------- init / finalize -------------------------------------------
__global__ void init_kernel(const float* __restrict__ hidden) {
    int i = blockIdx.x * 256 + threadIdx.x;
    if (i < B_ * H_)          g_h0[1][i]           = hidden[i];
    else if (i < 2 * B_ * H_) g_h1[1][i - B_ * H_] = hidden[i];
}

__global__ void final_kernel(float* __restrict__ out) {
    int i = blockIdx.x * 256 + threadIdx.x;
    if (i < B_ * H_)          out[i] = g_h0[1][i];
    else if (i < 2 * B_ * H_) out[i] = g_h1[1][i - B_ * H_];
}

// ---------------- r,z gates: sigmoid(comb @ [Wr;Wz].T + [br;bz]) ------------
// GEMM M=64, N=1024, K=512+Kx. Block: 64 rows x 16 cols, 256 threads, 4 out/thread.
__global__ void __launch_bounds__(256) rz2_kernel(GateArgs A0, GateArgs A1) {
    const GateArgs a = (blockIdx.z == 0) ? A0 : A1;
    const int K = 512 + a.Kx;

    __shared__ float sA[32][65];   // [kk][row]  (comb tile, transposed)
    __shared__ float sW[16][33];   // [n_local][kk]

    const int tid = threadIdx.x;
    const int row = tid & 63;
    const int cl  = tid >> 6;               // 0..3
    const int n0  = blockIdx.x * 16;

    float acc0 = 0.f, acc1 = 0.f, acc2 = 0.f, acc3 = 0.f;

    for (int k0 = 0; k0 < K; k0 += 32) {
        // stage comb tile: 64 x 32
#pragma unroll
        for (int i = 0; i < 8; i++) {
            int e  = i * 256 + tid;
            int rr = e >> 5;
            int kk = e & 31;
            int k  = k0 + kk;
            float v;
            if (k < 512) {
                v = a.hprev[rr * 512 + k];
            } else {
                const float* xr = a.idx ? (a.x + (size_t)a.idx[rr] * a.Kx)
                                        : (a.x + (size_t)rr * a.Kx);
                v = xr[k - 512];
            }
            sA[kk][rr] = v;
        }
        // stage weight tile: 16 x 32
#pragma unroll
        for (int i = 0; i < 2; i++) {
            int e  = i * 256 + tid;
            int nl = e >> 5;
            int kk = e & 31;
            int ng = n0 + nl;
            const float* wrow = (ng < 512) ? (a.Wr + (size_t)ng * K)
                                           : (a.Wz + (size_t)(ng - 512) * K);
            sW[nl][kk] = wrow[k0 + kk];
        }
        __syncthreads();
#pragma unroll
        for (int kk = 0; kk < 32; kk++) {
            float av = sA[kk][row];
            acc0 += av * sW[cl * 4 + 0][kk];
            acc1 += av * sW[cl * 4 + 1][kk];
            acc2 += av * sW[cl * 4 + 2][kk];
            acc3 += av * sW[cl * 4 + 3][kk];
        }
        __syncthreads();
    }

    float accs[4] = {acc0, acc1, acc2, acc3};
#pragma unroll
    for (int j = 0; j < 4; j++) {
        int ng = n0 + cl * 4 + j;
        float bias = (ng < 512) ? a.br[ng] : a.bz[ng - 512];
        float v = accs[j] + bias;
        a.out[row * 1024 + ng] = 1.0f / (1.0f + expf(-v));
    }
}

// ---------------- candidate + update: tanh([h*r, x] @ Wh.T + bh), blend -----
// GEMM M=64, N=512, K=512+Kx. Block: 64 rows x 16 cols, 256 threads.
__global__ void __launch_bounds__(256) h2_kernel(HArgs A0, HArgs A1) {
    const HArgs a = (blockIdx.z == 0) ? A0 : A1;
    const int K = 512 + a.Kx;

    __shared__ float sA[32][65];
    __shared__ float sW[16][33];

    const int tid = threadIdx.x;
    const int row = tid & 63;
    const int cl  = tid >> 6;
    const int n0  = blockIdx.x * 16;

    float acc0 = 0.f, acc1 = 0.f, acc2 = 0.f, acc3 = 0.f;

    for (int k0 = 0; k0 < K; k0 += 32) {
#pragma unroll
        for (int i = 0; i < 8; i++) {
            int e  = i * 256 + tid;
            int rr = e >> 5;
            int kk = e & 31;
            int k  = k0 + kk;
            float v;
            if (k < 512) {
                v = a.hprev[rr * 512 + k] * a.rz[rr * 1024 + k];   // h * r
            } else {
                const float* xr = a.idx ? (a.x + (size_t)a.idx[rr] * a.Kx)
                                        : (a.x + (size_t)rr * a.Kx);
                v = xr[k - 512];
            }
            sA[kk][rr] = v;
        }
#pragma unroll
        for (int i = 0; i < 2; i++) {
            int e  = i * 256 + tid;
            int nl = e >> 5;
            int kk = e & 31;
            int ng = n0 + nl;
            sW[nl][kk] = a.Wh[(size_t)ng * K + k0 + kk];
        }
        __syncthreads();
#pragma unroll
        for (int kk = 0; kk < 32; kk++) {
            float av = sA[kk][row];
            acc0 += av * sW[cl * 4 + 0][kk];
            acc1 += av * sW[cl * 4 + 1][kk];
            acc2 += av * sW[cl * 4 + 2][kk];
            acc3 += av * sW[cl * 4 + 3][kk];
        }
        __syncthreads();
    }

    float accs[4] = {acc0, acc1, acc2, acc3};
#pragma unroll
    for (int j = 0; j < 4; j++) {
        int ng = n0 + cl * 4 + j;
        float ht = tanhf(accs[j] + a.bh[ng]);
        float z  = a.rz[row * 1024 + 512 + ng];
        float hp = a.hprev[row * 512 + ng];
        float hn = (1.0f - z) * hp + z * ht;
        a.hout[row * 512 + ng] = hn;
        if (a.hout2) a.hout2[row * 512 + ng] = hn;
    }
}

// ---------------- logits: C[8192,10000] = h1all @ Wy.T + by -----------------
// BM=128, BN=64, BK=16, 256 threads, 8x4 per thread.
__global__ void __launch_bounds__(256) logits_kernel(
    const float* __restrict__ Wy, const float* __restrict__ by,
    float* __restrict__ out) {
    __shared__ float sA[16][132];   // [k][m]
    __shared__ float sB[16][68];    // [k][n]

    const int m0 = blockIdx.y * 128;
    const int v0 = blockIdx.x * 64;
    const int tid = threadIdx.x;
    const int tx = tid & 15;        // n groups of 4
    const int ty = tid >> 4;        // m groups of 8

    float acc[8][4];
#pragma unroll
    for (int i = 0; i < 8; i++)
#pragma unroll
        for (int j = 0; j < 4; j++) acc[i][j] = 0.f;

    for (int k0 = 0; k0 < 512; k0 += 16) {
        // A tile: 128x16 (2 float4 per thread)
#pragma unroll
        for (int i = 0; i < 2; i++) {
            int e  = i * 256 + tid;       // 0..511
            int m  = e >> 2;              // 0..127
            int kq = (e & 3) * 4;
            float4 v = *reinterpret_cast<const float4*>(
                &g_h1all[(size_t)(m0 + m) * 512 + k0 + kq]);
            sA[kq + 0][m] = v.x; sA[kq + 1][m] = v.y;
            sA[kq + 2][m] = v.z; sA[kq + 3][m] = v.w;
        }
        // B tile: 64x16 (1 float4 per thread)
        {
            int n  = tid >> 2;            // 0..63
            int kq = (tid & 3) * 4;
            int v  = v0 + n;
            float4 w = make_float4(0.f, 0.f, 0.f, 0.f);
            if (v < V_)
                w = *reinterpret_cast<const float4*>(&Wy[(size_t)v * 512 + k0 + kq]);
            sB[kq + 0][n] = w.x; sB[kq + 1][n] = w.y;
            sB[kq + 2][n] = w.z; sB[kq + 3][n] = w.w;
        }
        __syncthreads();
#pragma unroll
        for (int kk = 0; kk < 16; kk++) {
            float4 a0 = *reinterpret_cast<const float4*>(&sA[kk][ty * 8]);
            float4 a1 = *reinterpret_cast<const float4*>(&sA[kk][ty * 8 + 4]);
            float4 b  = *reinterpret_cast<const float4*>(&sB[kk][tx * 4]);
            float av[8] = {a0.x, a0.y, a0.z, a0.w, a1.x, a1.y, a1.z, a1.w};
            float bv[4] = {b.x, b.y, b.z, b.w};
#pragma unroll
            for (int i = 0; i < 8; i++)
#pragma unroll
                for (int j = 0; j < 4; j++) acc[i][j] += av[i] * bv[j];
        }
        __syncthreads();
    }

    int vb = v0 + tx * 4;
    if (vb < V_) {
        float4 bias = *reinterpret_cast<const float4*>(&by[vb]);
#pragma unroll
        for (int i = 0; i < 8; i++) {
            float4 r;
            r.x = acc[i][0] + bias.x;
            r.y = acc[i][1] + bias.y;
            r.z = acc[i][2] + bias.z;
            r.w = acc[i][3] + bias.w;
            *reinterpret_cast<float4*>(&out[(size_t)(m0 + ty * 8 + i) * V_ + vb]) = r;
        }
    }
}

// ---------------- host driver (graph-capturable) ----------------------------
extern "C" void kernel_launch(void* const* d_in, const int* in_sizes, int n_in,
                              void* d_out, int out_size) {
    const int*   inputs = (const int*)d_in[0];
    const float* hidden = (const float*)d_in[1];
    const float* emb    = (const float*)d_in[2];
    const float* W_r0 = (const float*)d_in[3];  const float* b_r0 = (const float*)d_in[4];
    const float* W_z0 = (const float*)d_in[5];  const float* b_z0 = (const float*)d_in[6];
    const float* W_h0 = (const float*)d_in[7];  const float* b_h0 = (const float*)d_in[8];
    const float* W_r1 = (const float*)d_in[9];  const float* b_r1 = (const float*)d_in[10];
    const float* W_z1 = (const float*)d_in[11]; const float* b_z1 = (const float*)d_in[12];
    const float* W_h1 = (const float*)d_in[13]; const float* b_h1 = (const float*)d_in[14];
    const float* Wy   = (const float*)d_in[15]; const float* by   = (const float*)d_in[16];
    float* out = (float*)d_out;

    float *h0b, *h1b, *rz0b, *rz1b, *h1all;
    cudaGetSymbolAddress((void**)&h0b,   g_h0);
    cudaGetSymbolAddress((void**)&h1b,   g_h1);
    cudaGetSymbolAddress((void**)&rz0b,  g_rz0);
    cudaGetSymbolAddress((void**)&rz1b,  g_rz1);
    cudaGetSymbolAddress((void**)&h1all, g_h1all);

    float* h0p[2] = {h0b, h0b + B_ * H_};
    float* h1p[2] = {h1b, h1b + B_ * H_};

    auto rz0A = [&](int t) {
        GateArgs a; a.hprev = h0p[(t + 1) & 1]; a.x = emb; a.idx = inputs + t * B_;
        a.Wr = W_r0; a.br = b_r0; a.Wz = W_z0; a.bz = b_z0; a.out = rz0b; a.Kx = E_;
        return a;
    };
    auto rz1A = [&](int t) {
        GateArgs a; a.hprev = h1p[(t + 1) & 1]; a.x = h0p[t & 1]; a.idx = nullptr;
        a.Wr = W_r1; a.br = b_r1; a.Wz = W_z1; a.bz = b_z1; a.out = rz1b; a.Kx = H_;
        return a;
    };
    auto h0A = [&](int t) {
        HArgs a; a.hprev = h0p[(t + 1) & 1]; a.x = emb; a.idx = inputs + t * B_;
        a.rz = rz0b; a.Wh = W_h0; a.bh = b_h0;
        a.hout = h0p[t & 1]; a.hout2 = nullptr; a.Kx = E_;
        return a;
    };
    auto h1A = [&](int t) {
        HArgs a; a.hprev = h1p[(t + 1) & 1]; a.x = h0p[t & 1]; a.idx = nullptr;
        a.rz = rz1b; a.Wh = W_h1; a.bh = b_h1;
        a.hout = h1p[t & 1]; a.hout2 = h1all + (size_t)t * B_ * H_; a.Kx = H_;
        return a;
    };

    GateArgs gdummy = {}; HArgs hdummy = {};

    init_kernel<<<256, 256>>>(hidden);

    // pipelined schedule:
    //   RZ0(0); for t: { H0(t) || H1(t-1) } ; { RZ1(t) || RZ0(t+1) } ; then H1(127)
    rz2_kernel<<<dim3(64, 1, 1), 256>>>(rz0A(0), gdummy);
    for (int t = 0; t < S_; t++) {
        if (t == 0) h2_kernel<<<dim3(32, 1, 1), 256>>>(h0A(0), hdummy);
        else        h2_kernel<<<dim3(32, 1, 2), 256>>>(h0A(t), h1A(t - 1));
        if (t < S_ - 1) rz2_kernel<<<dim3(64, 1, 2), 256>>>(rz1A(t), rz0A(t + 1));
        else            rz2_kernel<<<dim3(64, 1, 1), 256>>>(rz1A(t), gdummy);
    }
    h2_kernel<<<dim3(32, 1, 1), 256>>>(h1A(S_ - 1), hdummy);

    logits_kernel<<<dim3((V_ + 63) / 64, (S_ * B_) / 128), 256>>>(Wy, by, out);
    final_kernel<<<256, 256>>>(out + (size_t)S_ * B_ * V_);
}

// round 5
// speedup vs baseline: 4.2984x; 4.2984x over previous
#include <cuda_runtime.h>
#include <math.h>

#define S_ 128
#define B_ 64
#define V_ 10000
#define E_ 256
#define H_ 512
#define GRID_P 128
#define THR_P 256

// ---------------- scratch (device globals; no allocations allowed) ----------
__device__ float g_h0[2][B_ * H_];
__device__ float g_h1[2][B_ * H_];
__device__ float g_rzp[2][4][B_ * 2 * H_];  // r|z pre-activation partials (4 k-splits)
__device__ float g_hp[2][8][B_ * H_];       // h_tilda pre-activation partials (8 k-splits)
__device__ float g_h1all[S_ * B_ * H_];     // all h1(t) for the logits GEMM
__device__ unsigned int g_arrive;           // grid-barrier arrival counter

struct Params {
    const int* inputs; const float* emb;
    const float* Wr0; const float* br0; const float* Wz0; const float* bz0;
    const float* Wh0; const float* bh0;
    const float* Wr1; const float* br1; const float* Wz1; const float* bz1;
    const float* Wh1; const float* bh1;
};

__device__ __forceinline__ float sigm(float x) {
    return __fdividef(1.0f, 1.0f + __expf(-x));
}

#define LD4(p) (*reinterpret_cast<const float4*>(p))

// ---------------- grid barrier (monotonic counter, all CTAs resident) -------
// __threadfence() (gpu scope -> CCTL.IVALL) by ALL threads before arrive/wait:
// writers' stores reach L2 before arrival; readers' L1 is invalidated before
// release; spinners issue no polluting loads. Safe and coherent.
__device__ __forceinline__ void gbar(unsigned int& barN) {
    barN += GRID_P;
    __threadfence();
    __syncthreads();
    if (threadIdx.x == 0) {
        atomicAdd(&g_arrive, 1u);
        unsigned int v;
        do {
            asm volatile("ld.acquire.gpu.u32 %0, [%1];" : "=r"(v) : "l"(&g_arrive) : "memory");
            if (v < barN) __nanosleep(64);
        } while (v < barN);
    }
    __syncthreads();
}

// ---------------- generic partial-GEMM phase ---------------------------------
// out(row, n) = sum_{k in chunk} A[row,k] * W[n,k]
// MODE 0: RZ layer1  A=[h1(t-1) | h0(t)]          W=[Wr1;Wz1] K=1024 OUTN=1024
// MODE 1: RZ layer0  A=[h0(t)   | emb(idx_{t+1})] W=[Wr0;Wz0] K=768  OUTN=1024
// MODE 2: HC layer0  A=[h0(t-1)*r0 | emb(idx_t)]  W=Wh0       K=768  OUTN=512
// MODE 3: HC layer1  A=[h1(t-2)*r1 | h0(t-1)]     W=Wh1       K=1024 OUTN=512
// Tile: 64 rows x 64 cols, 256 threads, 4x4 per thread, Ktile=32.
template <int MODE>
__device__ void gemm_phase(const Params& Pp, int t, int n0, int kstart, int ktiles,
                           float* __restrict__ outp,
                           float (&sA)[32][68], float (&sB)[32][68]) {
    constexpr int OUTN = (MODE < 2) ? 1024 : 512;
    const int tid = threadIdx.x;
    const int tx = tid & 15, ty = tid >> 4;

    const float* __restrict__ h0cur   = g_h0[t & 1];
    const float* __restrict__ h0prev  = g_h0[(t + 1) & 1];
    const float* __restrict__ h1prev  = g_h1[(t + 1) & 1];
    const float* __restrict__ h1prev2 = g_h1[t & 1];

    float acc[4][4];
#pragma unroll
    for (int i = 0; i < 4; i++)
#pragma unroll
        for (int j = 0; j < 4; j++) acc[i][j] = 0.f;

    for (int kt = 0; kt < ktiles; kt++) {
        const int kb = kstart + kt * 32;
        // ---- stage A: 64 rows x 32 k (2 float4 per thread, coalesced) ----
#pragma unroll
        for (int i = 0; i < 2; i++) {
            int e  = i * 256 + tid;       // 0..511
            int rr = e >> 3;              // 0..63
            int kl = (e & 7) * 4;         // 0,4,..28
            int kq = kb + kl;
            float4 v;
            if (MODE == 0) {
                v = (kq < 512) ? LD4(h1prev + rr * 512 + kq)
                               : LD4(h0cur + rr * 512 + (kq - 512));
            } else if (MODE == 1) {
                if (kq < 512) v = LD4(h0cur + rr * 512 + kq);
                else {
                    int tok = Pp.inputs[(t + 1) * B_ + rr];
                    v = LD4(Pp.emb + (size_t)tok * E_ + (kq - 512));
                }
            } else if (MODE == 2) {
                if (kq < 512) {
                    float4 h  = LD4(h0prev + rr * 512 + kq);
                    float4 p0 = LD4(&g_rzp[1][0][rr * 1024 + kq]);
                    float4 p1 = LD4(&g_rzp[1][1][rr * 1024 + kq]);
                    float4 p2 = LD4(&g_rzp[1][2][rr * 1024 + kq]);
                    float4 p3 = LD4(&g_rzp[1][3][rr * 1024 + kq]);
                    float4 bb = LD4(Pp.br0 + kq);
                    v.x = h.x * sigm(p0.x + p1.x + p2.x + p3.x + bb.x);
                    v.y = h.y * sigm(p0.y + p1.y + p2.y + p3.y + bb.y);
                    v.z = h.z * sigm(p0.z + p1.z + p2.z + p3.z + bb.z);
                    v.w = h.w * sigm(p0.w + p1.w + p2.w + p3.w + bb.w);
                } else {
                    int tok = Pp.inputs[t * B_ + rr];
                    v = LD4(Pp.emb + (size_t)tok * E_ + (kq - 512));
                }
            } else {  // MODE == 3
                if (kq < 512) {
                    float4 h  = LD4(h1prev2 + rr * 512 + kq);
                    float4 p0 = LD4(&g_rzp[0][0][rr * 1024 + kq]);
                    float4 p1 = LD4(&g_rzp[0][1][rr * 1024 + kq]);
                    float4 p2 = LD4(&g_rzp[0][2][rr * 1024 + kq]);
                    float4 p3 = LD4(&g_rzp[0][3][rr * 1024 + kq]);
                    float4 bb = LD4(Pp.br1 + kq);
                    v.x = h.x * sigm(p0.x + p1.x + p2.x + p3.x + bb.x);
                    v.y = h.y * sigm(p0.y + p1.y + p2.y + p3.y + bb.y);
                    v.z = h.z * sigm(p0.z + p1.z + p2.z + p3.z + bb.z);
                    v.w = h.w * sigm(p0.w + p1.w + p2.w + p3.w + bb.w);
                } else {
                    v = LD4(h0prev + rr * 512 + (kq - 512));
                }
            }
            sA[kl + 0][rr] = v.x; sA[kl + 1][rr] = v.y;
            sA[kl + 2][rr] = v.z; sA[kl + 3][rr] = v.w;
        }
        // ---- stage B: 64 cols x 32 k (2 float4 per thread, coalesced) ----
#pragma unroll
        for (int i = 0; i < 2; i++) {
            int e  = i * 256 + tid;
            int nl = e >> 3;              // 0..63
            int kl = (e & 7) * 4;
            int kq = kb + kl;
            int ng = n0 + nl;
            const float* wrow;
            if (MODE == 0)
                wrow = (ng < 512) ? Pp.Wr1 + (size_t)ng * 1024
                                  : Pp.Wz1 + (size_t)(ng - 512) * 1024;
            else if (MODE == 1)
                wrow = (ng < 512) ? Pp.Wr0 + (size_t)ng * 768
                                  : Pp.Wz0 + (size_t)(ng - 512) * 768;
            else if (MODE == 2)
                wrow = Pp.Wh0 + (size_t)ng * 768;
            else
                wrow = Pp.Wh1 + (size_t)ng * 1024;
            float4 w = LD4(wrow + kq);
            sB[kl + 0][nl] = w.x; sB[kl + 1][nl] = w.y;
            sB[kl + 2][nl] = w.z; sB[kl + 3][nl] = w.w;
        }
        __syncthreads();
#pragma unroll
        for (int kk = 0; kk < 32; kk++) {
            float4 a = *reinterpret_cast<const float4*>(&sA[kk][ty * 4]);
            float4 b = *reinterpret_cast<const float4*>(&sB[kk][tx * 4]);
            acc[0][0] += a.x * b.x; acc[0][1] += a.x * b.y; acc[0][2] += a.x * b.z; acc[0][3] += a.x * b.w;
            acc[1][0] += a.y * b.x; acc[1][1] += a.y * b.y; acc[1][2] += a.y * b.z; acc[1][3] += a.y * b.w;
            acc[2][0] += a.z * b.x; acc[2][1] += a.z * b.y; acc[2][2] += a.z * b.z; acc[2][3] += a.z * b.w;
            acc[3][0] += a.w * b.x; acc[3][1] += a.w * b.y; acc[3][2] += a.w * b.z; acc[3][3] += a.w * b.w;
        }
        __syncthreads();
    }
#pragma unroll
    for (int i = 0; i < 4; i++) {
        float4 o = make_float4(acc[i][0], acc[i][1], acc[i][2], acc[i][3]);
        *reinterpret_cast<float4*>(&outp[(size_t)(ty * 4 + i) * OUTN + n0 + tx * 4]) = o;
    }
}

// ---------------- finalize h: tanh + blend, write h1all ----------------------
__device__ __forceinline__ void hfin(const Params& P, int t, bool a0, bool a1) {
    int id  = blockIdx.x * THR_P + threadIdx.x;  // 0..32767 == 64 x 512
    int row = id >> 9;
    int n   = id & 511;
    if (a0) {  // h0(t)
        float acc = 0.f;
#pragma unroll
        for (int ks = 0; ks < 8; ks++) acc += g_hp[0][ks][row * 512 + n];
        float ht = tanhf(acc + P.bh0[n]);
        float zp = 0.f;
#pragma unroll
        for (int ks = 0; ks < 4; ks++) zp += g_rzp[1][ks][row * 1024 + 512 + n];
        float z  = sigm(zp + P.bz0[n]);
        float hp = g_h0[(t + 1) & 1][row * 512 + n];
        g_h0[t & 1][row * 512 + n] = (1.f - z) * hp + z * ht;
    }
    if (a1) {  // h1(t-1)
        float acc = 0.f;
#pragma unroll
        for (int ks = 0; ks < 8; ks++) acc += g_hp[1][ks][row * 512 + n];
        float ht = tanhf(acc + P.bh1[n]);
        float zp = 0.f;
#pragma unroll
        for (int ks = 0; ks < 4; ks++) zp += g_rzp[0][ks][row * 1024 + 512 + n];
        float z  = sigm(zp + P.bz1[n]);
        float hp = g_h1[t & 1][row * 512 + n];
        float hn = (1.f - z) * hp + z * ht;
        g_h1[(t + 1) & 1][row * 512 + n] = hn;
        g_h1all[(size_t)(t - 1) * B_ * H_ + row * 512 + n] = hn;
    }
}

// ---------------- the persistent recurrence kernel ---------------------------
__global__ void __launch_bounds__(THR_P, 1) recur_kernel(Params P) {
    __shared__ float sA[32][68];
    __shared__ float sB[32][68];
    unsigned int barN = 0;
    const int bid  = blockIdx.x;
    const int half = bid >> 6;           // 0: layer-A role, 1: layer-B role
    const int r    = bid & 63;
    const int rz_n0 = (r >> 2) * 64, rz_ks = r & 3;   // 16 col-tiles x 4 k-splits
    const int hc_n0 = (r >> 3) * 64, hc_ks = r & 7;   // 8 col-tiles x 8 k-splits

    // pre: rz0(0)  (t = -1 -> uses init hidden at parity 1, idx row 0)
    if (half == 1)
        gemm_phase<1>(P, -1, rz_n0, rz_ks * 192, 6, g_rzp[1][rz_ks], sA, sB);
    gbar(barN);

    for (int t = 0; t <= S_; t++) {
        // HC: h0(t) and h1(t-1) partials
        if (half == 0) {
            if (t <= S_ - 1)
                gemm_phase<2>(P, t, hc_n0, hc_ks * 96, 3, g_hp[0][hc_ks], sA, sB);
        } else {
            if (t >= 1)
                gemm_phase<3>(P, t, hc_n0, hc_ks * 128, 4, g_hp[1][hc_ks], sA, sB);
        }
        gbar(barN);
        // HFIN: finalize h0(t), h1(t-1)
        hfin(P, t, t <= S_ - 1, t >= 1);
        gbar(barN);
        // RZ: rz1(t) and rz0(t+1) partials
        if (t < S_) {
            if (half == 0)
                gemm_phase<0>(P, t, rz_n0, rz_ks * 256, 8, g_rzp[0][rz_ks], sA, sB);
            else if (t <= S_ - 2)
                gemm_phase<1>(P, t, rz_n0, rz_ks * 192, 6, g_rzp[1][rz_ks], sA, sB);
            gbar(barN);
        }
    }
}

// ---------------- init / finalize -------------------------------------------
__global__ void init_kernel(const float* __restrict__ hidden) {
    int i = blockIdx.x * 256 + threadIdx.x;
    if (i == 0) g_arrive = 0u;
    if (i < B_ * H_)          g_h0[1][i]           = hidden[i];
    else if (i < 2 * B_ * H_) g_h1[1][i - B_ * H_] = hidden[i];
}

__global__ void final_kernel(float* __restrict__ out) {
    int i = blockIdx.x * 256 + threadIdx.x;
    if (i < B_ * H_)          out[i] = g_h0[1][i];
    else if (i < 2 * B_ * H_) out[i] = g_h1[1][i - B_ * H_];
}

// ---------------- logits: C[8192,10000] = h1all @ Wy.T + by -----------------
// BM=128, BN=64, BK=16, 256 threads, 8x4 per thread. (known-good from R1/R2)
__global__ void __launch_bounds__(256) logits_kernel(
    const float* __restrict__ Wy, const float* __restrict__ by,
    float* __restrict__ out) {
    __shared__ float sA[16][132];
    __shared__ float sB[16][68];

    const int m0 = blockIdx.y * 128;
    const int v0 = blockIdx.x * 64;
    const int tid = threadIdx.x;
    const int tx = tid & 15;
    const int ty = tid >> 4;

    float acc[8][4];
#pragma unroll
    for (int i = 0; i < 8; i++)
#pragma unroll
        for (int j = 0; j < 4; j++) acc[i][j] = 0.f;

    for (int k0 = 0; k0 < 512; k0 += 16) {
#pragma unroll
        for (int i = 0; i < 2; i++) {
            int e  = i * 256 + tid;
            int m  = e >> 2;
            int kq = (e & 3) * 4;
            float4 v = *reinterpret_cast<const float4*>(
                &g_h1all[(size_t)(m0 + m) * 512 + k0 + kq]);
            sA[kq + 0][m] = v.x; sA[kq + 1][m] = v.y;
            sA[kq + 2][m] = v.z; sA[kq + 3][m] = v.w;
        }
        {
            int n  = tid >> 2;
            int kq = (tid & 3) * 4;
            int v  = v0 + n;
            float4 w = make_float4(0.f, 0.f, 0.f, 0.f);
            if (v < V_)
                w = *reinterpret_cast<const float4*>(&Wy[(size_t)v * 512 + k0 + kq]);
            sB[kq + 0][n] = w.x; sB[kq + 1][n] = w.y;
            sB[kq + 2][n] = w.z; sB[kq + 3][n] = w.w;
        }
        __syncthreads();
#pragma unroll
        for (int kk = 0; kk < 16; kk++) {
            float4 a0 = *reinterpret_cast<const float4*>(&sA[kk][ty * 8]);
            float4 a1 = *reinterpret_cast<const float4*>(&sA[kk][ty * 8 + 4]);
            float4 b  = *reinterpret_cast<const float4*>(&sB[kk][tx * 4]);
            float av[8] = {a0.x, a0.y, a0.z, a0.w, a1.x, a1.y, a1.z, a1.w};
            float bv[4] = {b.x, b.y, b.z, b.w};
#pragma unroll
            for (int i = 0; i < 8; i++)
#pragma unroll
                for (int j = 0; j < 4; j++) acc[i][j] += av[i] * bv[j];
        }
        __syncthreads();
    }

    int vb = v0 + tx * 4;
    if (vb < V_) {
        float4 bias = *reinterpret_cast<const float4*>(&by[vb]);
#pragma unroll
        for (int i = 0; i < 8; i++) {
            float4 rr;
            rr.x = acc[i][0] + bias.x;
            rr.y = acc[i][1] + bias.y;
            rr.z = acc[i][2] + bias.z;
            rr.w = acc[i][3] + bias.w;
            *reinterpret_cast<float4*>(&out[(size_t)(m0 + ty * 8 + i) * V_ + vb]) = rr;
        }
    }
}

// ---------------- host driver (graph-capturable) ----------------------------
extern "C" void kernel_launch(void* const* d_in, const int* in_sizes, int n_in,
                              void* d_out, int out_size) {
    Params P;
    P.inputs = (const int*)d_in[0];
    const float* hidden = (const float*)d_in[1];
    P.emb = (const float*)d_in[2];
    P.Wr0 = (const float*)d_in[3];  P.br0 = (const float*)d_in[4];
    P.Wz0 = (const float*)d_in[5];  P.bz0 = (const float*)d_in[6];
    P.Wh0 = (const float*)d_in[7];  P.bh0 = (const float*)d_in[8];
    P.Wr1 = (const float*)d_in[9];  P.br1 = (const float*)d_in[10];
    P.Wz1 = (const float*)d_in[11]; P.bz1 = (const float*)d_in[12];
    P.Wh1 = (const float*)d_in[13]; P.bh1 = (const float*)d_in[14];
    const float* Wy = (const float*)d_in[15];
    const float* by = (const float*)d_in[16];
    float* out = (float*)d_out;

    init_kernel<<<256, 256>>>(hidden);
    recur_kernel<<<GRID_P, THR_P>>>(P);
    logits_kernel<<<dim3((V_ + 63) / 64, (S_ * B_) / 128), 256>>>(Wy, by, out);
    final_kernel<<<256, 256>>>(out + (size_t)S_ * B_ * V_);
}